// round 16
// baseline (speedup 1.0000x reference)
#include <cuda_runtime.h>
#include <math.h>
#include <float.h>

#define NPIL 60000
#define PPTS 32
#define SBLK 469   // k_stats: 128 thr/block, thread-per-pillar, pipelined staging

// moment partials, entry-major for coalesced reduction:
// entry t: [0..3]=M1(sum u), [4..13]=M2 tri4, [14..37]=X[i*6+j]=sum(S_i*alpha_j),
//          [38..58]=A2 tri6 (nv*alpha_a*alpha_b), [59..64]=A1 (nv*alpha_j)
static __device__ float g_part[65][SBLK];
// per-channel folded params, 16 floats each (4 float4s)
static __device__ float g_params[64 * 16];
// per-pillar mean + center: [2i]={mx,my,mz,-}, [2i+1]={cx,cy,cz,-}
static __device__ float4 g_pm[NPIL * 2];

__device__ __forceinline__ float wredsum(float v) {
#pragma unroll
    for (int s = 16; s > 0; s >>= 1) v += __shfl_xor_sync(0xffffffffu, v, s);
    return v;
}

// ---------------------------------------------------------------------------
// k_stats: thread-per-pillar compute, coalesced smem staging, SOFTWARE
// PIPELINED: chunk ch+1's 8 LDGs are issued into registers BEFORE processing
// chunk ch, so DRAM latency overlaps compute. Double-buffered tile (no WAR).
//   store(ch) ; syncwarp ; prefetch LDG(ch+1) ; process(ch)
// Staging: 8 LDGs/chunk, each covering 4 pillars x 8 points (4 full 128B
// lines). Tile row stride 9 float4 -> conflict-free STS/LDS (quarter-warp).
// Epilogue: all 65 moment entries computed on the fly, warp-reduced once
// per 32 pillars.
// ---------------------------------------------------------------------------
__global__ void __launch_bounds__(128) k_stats(const float4* __restrict__ pts,
                                               const int* __restrict__ nvs,
                                               const int4* __restrict__ coords) {
    __shared__ float4 tile[4][2][32][9];  // [warp][buf][pillar][pt+pad] ~36.9KB
    __shared__ float sE[4][65];
    const int lane = threadIdx.x & 31;
    const int warp = threadIdx.x >> 5;
    const int warp_base = blockIdx.x * 128 + warp * 32;
    const bool wok = (warp_base < NPIL);      // warp-uniform (60000 = 468*128+96)
    const int i = warp_base + lane;           // this thread's pillar

    float S[4]  = {0.0f, 0.0f, 0.0f, 0.0f};
    float M2[10];
#pragma unroll
    for (int k = 0; k < 10; k++) M2[k] = 0.0f;
    float al[6] = {0.0f, 0.0f, 0.0f, 0.0f, 0.0f, 0.0f};
    float nvf = 0.0f;

    if (wok) {
        const int gsub = lane >> 3;           // 0..3: pillar-within-group
        const int psub = lane & 7;            // 0..7: point-within-chunk
        const int nv = nvs[i];
        const int4 c = coords[i];
        float tx = 0.0f, ty = 0.0f, tz = 0.0f;

        float4 r[8];
        // prologue: LDG chunk 0 into registers
#pragma unroll
        for (int g = 0; g < 8; g++)
            r[g] = pts[(warp_base + g * 4 + gsub) * PPTS + psub];

#pragma unroll
        for (int ch = 0; ch < 4; ch++) {
            const int buf = ch & 1;
            // store chunk ch (STS waits on its LDGs -- overlapped by now)
#pragma unroll
            for (int g = 0; g < 8; g++)
                tile[warp][buf][g * 4 + gsub][psub] = r[g];
            __syncwarp();
            // prefetch chunk ch+1 (no dependency -> issues without stall)
            if (ch < 3) {
#pragma unroll
                for (int g = 0; g < 8; g++)
                    r[g] = pts[(warp_base + g * 4 + gsub) * PPTS + (ch + 1) * 8 + psub];
            }
            // process chunk ch from smem (overlaps chunk ch+1's DRAM latency)
#pragma unroll
            for (int p = 0; p < 8; p++) {
                const float4 q = tile[warp][buf][lane][p];
                const int pg = ch * 8 + p;
                const float m = (pg < nv) ? 1.0f : 0.0f;
                tx += q.x; ty += q.y; tz += q.z;
                const float ux = q.x * m, uy = q.y * m, uz = q.z * m, uw = q.w * m;
                S[0] += ux; S[1] += uy; S[2] += uz; S[3] += uw;
                M2[0] = fmaf(ux, ux, M2[0]); M2[1] = fmaf(ux, uy, M2[1]);
                M2[2] = fmaf(ux, uz, M2[2]); M2[3] = fmaf(ux, uw, M2[3]);
                M2[4] = fmaf(uy, uy, M2[4]); M2[5] = fmaf(uy, uz, M2[5]);
                M2[6] = fmaf(uy, uw, M2[6]); M2[7] = fmaf(uz, uz, M2[7]);
                M2[8] = fmaf(uz, uw, M2[8]); M2[9] = fmaf(uw, uw, M2[9]);
            }
            __syncwarp();   // tile reads done before next iteration's STS
        }

        nvf = (float)nv;
        const float inv = 1.0f / nvf;
        al[0] = tx * inv;                     // mean over ALL 32 points, / nv (ref)
        al[1] = ty * inv;
        al[2] = tz * inv;
        al[3] = (float)c.w * 0.2f + 0.1f;
        al[4] = (float)c.z * 0.2f - 39.9f;
        al[5] = (float)c.y * 4.0f - 1.0f;
        g_pm[2 * i]     = make_float4(al[0], al[1], al[2], 0.0f);
        g_pm[2 * i + 1] = make_float4(al[3], al[4], al[5], 0.0f);
    }

    // warp-reduce all 65 entries (inactive warps contribute zeros)
#pragma unroll
    for (int k = 0; k < 4; k++) {
        const float v = wredsum(S[k]);
        if (lane == 0) sE[warp][k] = v;
    }
#pragma unroll
    for (int k = 0; k < 10; k++) {
        const float v = wredsum(M2[k]);
        if (lane == 0) sE[warp][4 + k] = v;
    }
#pragma unroll
    for (int a = 0; a < 4; a++)
#pragma unroll
        for (int jj = 0; jj < 6; jj++) {
            const float v = wredsum(S[a] * al[jj]);
            if (lane == 0) sE[warp][14 + a * 6 + jj] = v;
        }
#pragma unroll
    for (int a = 0; a < 6; a++)
#pragma unroll
        for (int b = 0; b < 6; b++) {
            if (b < a) continue;
            const float v = wredsum(nvf * al[a] * al[b]);
            if (lane == 0) sE[warp][38 + (a * 6 - a * (a - 1) / 2 + (b - a))] = v;
        }
#pragma unroll
    for (int jj = 0; jj < 6; jj++) {
        const float v = wredsum(nvf * al[jj]);
        if (lane == 0) sE[warp][59 + jj] = v;
    }
    __syncthreads();

    const int t = threadIdx.x;
    if (t < 65) {
        g_part[t][blockIdx.x] = (sE[0][t] + sE[1][t]) + (sE[2][t] + sE[3][t]);
    }
}

// ---------------------------------------------------------------------------
// k_bn: parallel reduce of g_part (8 threads per entry), then per-channel
// BN-folded param derivation in double precision.
// ---------------------------------------------------------------------------
__global__ void __launch_bounds__(544) k_bn(const float* __restrict__ W,
                                            const float* __restrict__ gamma,
                                            const float* __restrict__ beta) {
    __shared__ float sp8[65][8];
    __shared__ float s_acc[65];
    const int t = threadIdx.x;
    if (t < 520) {
        const int e = t >> 3;
        const int s = t & 7;
        const float* row = g_part[e];
        float acc = 0.0f;
        for (int k = 0; k < 59; k++) {            // 469 <= 8*59
            const int idx = s + 8 * k;
            if (idx < SBLK) acc += row[idx];
        }
        sp8[e][s] = acc;
    }
    __syncthreads();
    if (t < 65) {
        const float* r = sp8[t];
        s_acc[t] = ((r[0] + r[1]) + (r[2] + r[3])) + ((r[4] + r[5]) + (r[6] + r[7]));
    }
    __syncthreads();
    if (t >= 64) return;
    const int o = t;

    const int pidx[10] = {0, 1, 2, 3, 0, 1, 2, 0, 1, 2};
    const int aidx[10] = {-1, -1, -1, -1, 0, 1, 2, 3, 4, 5};

    double w[10];
#pragma unroll
    for (int cc = 0; cc < 10; cc++) w[cc] = (double)W[o * 10 + cc];
    const double NP = (double)NPIL * (double)PPTS;

    double mean = 0.0;
#pragma unroll
    for (int a = 0; a < 10; a++) {
        double g1 = (double)s_acc[pidx[a]];
        if (aidx[a] >= 0) g1 -= (double)s_acc[59 + aidx[a]];
        mean += w[a] * g1;
    }
    mean /= NP;

    double e2 = 0.0;
#pragma unroll
    for (int a = 0; a < 10; a++) {
#pragma unroll
        for (int b = 0; b < 10; b++) {
            if (b < a) continue;
            const int pa = pidx[a], pb = pidx[b];
            const int i4 = (pa <= pb) ? pa : pb;
            const int j4 = (pa <= pb) ? pb : pa;
            double g2 = (double)s_acc[4 + (i4 * 4 - i4 * (i4 - 1) / 2 + (j4 - i4))];
            if (aidx[a] >= 0) g2 -= (double)s_acc[14 + pb * 6 + aidx[a]];
            if (aidx[b] >= 0) g2 -= (double)s_acc[14 + pa * 6 + aidx[b]];
            if (aidx[a] >= 0 && aidx[b] >= 0) {
                const int i6 = (aidx[a] <= aidx[b]) ? aidx[a] : aidx[b];
                const int j6 = (aidx[a] <= aidx[b]) ? aidx[b] : aidx[a];
                g2 += (double)s_acc[38 + (i6 * 6 - i6 * (i6 - 1) / 2 + (j6 - i6))];
            }
            e2 += w[a] * w[b] * g2 * ((a == b) ? 1.0 : 2.0);
        }
    }
    e2 /= NP;

    const double var = e2 - mean * mean;
    const double aa = (double)gamma[o] / sqrt(var + 1e-3);
    const double bb = (double)beta[o] - mean * aa;
    float* p = g_params + o * 16;
    p[0]  = (float)(aa * (w[0] + w[4] + w[7]));
    p[1]  = (float)(aa * (w[1] + w[5] + w[8]));
    p[2]  = (float)(aa * (w[2] + w[6] + w[9]));
    p[3]  = (float)(aa * w[3]);
    p[4]  = (float)(aa * w[4]);
    p[5]  = (float)(aa * w[5]);
    p[6]  = (float)(aa * w[6]);
    p[7]  = (float)(aa * w[7]);
    p[8]  = (float)(aa * w[8]);
    p[9]  = (float)(aa * w[9]);
    p[10] = (float)bb;
    p[11] = 0.0f;
    p[12] = 0.0f; p[13] = 0.0f; p[14] = 0.0f; p[15] = 0.0f;
}

// ---------------------------------------------------------------------------
// k_out: warp = pillar, SINGLE wave (grid 592 = 4 blocks/SM resident).
// Dup-fill via SHUFFLE broadcast of point 0 (valid duplicate; nv>=1 per
// reference randint(1,P+1)) -> one syncwarp per pillar, fixed-step-4 inner
// loop with no remainder. max_p(pb + d_p) == pb + max_p(d_p).
// ---------------------------------------------------------------------------
__global__ void __launch_bounds__(256) k_out(const float4* __restrict__ pts,
                                             const int* __restrict__ nvs,
                                             float* __restrict__ out) {
    __shared__ float4 sp[8][32];
    const int lane = threadIdx.x & 31;
    const int warp = threadIdx.x >> 5;
    const int gw = blockIdx.x * 8 + warp;
    const int nw = gridDim.x * 8;

    const float4* pp = (const float4*)g_params;
    const float4 wc0 = pp[lane * 4 + 0];
    const float4 m0v = pp[lane * 4 + 1];          // {aW4,aW5,aW6,aW7}
    const float4 t0v = pp[lane * 4 + 2];          // {aW8,aW9,b,pad}
    const float4 wc1 = pp[(lane + 32) * 4 + 0];
    const float4 m1v = pp[(lane + 32) * 4 + 1];
    const float4 t1v = pp[(lane + 32) * 4 + 2];

    int i = gw;
    if (i >= NPIL) return;
    float4 q = pts[i * PPTS + lane];
    int nv = nvs[i];

    for (;;) {
        // dup-fill value: point 0 broadcast (always valid)
        const float fx = __shfl_sync(0xffffffffu, q.x, 0);
        const float fy = __shfl_sync(0xffffffffu, q.y, 0);
        const float fz = __shfl_sync(0xffffffffu, q.z, 0);
        const float fw = __shfl_sync(0xffffffffu, q.w, 0);
        sp[warp][lane] = (lane < nv) ? q : make_float4(fx, fy, fz, fw);
        const float4 pm = g_pm[2 * i];        // consumed after the loop
        const float4 pc = g_pm[2 * i + 1];
        __syncwarp();

        const int inext = i + nw;
        const bool more = inext < NPIL;
        float4 qn; int nvn = 0;
        if (more) {                            // prefetch next pillar
            qn = pts[inext * PPTS + lane];
            nvn = nvs[inext];
        }

        const float4* s4 = sp[warp];
        float a0 = -FLT_MAX, b0 = -FLT_MAX, a1 = -FLT_MAX, b1 = -FLT_MAX;
        for (int p = 0; p < nv; p += 4) {      // p<=28 -> p+3<=31 always in-tile
            float4 r0 = s4[p];
            float4 r1 = s4[p + 1];
            a0 = fmaxf(a0, fmaf(r0.x, wc0.x, fmaf(r0.y, wc0.y, fmaf(r0.z, wc0.z, r0.w * wc0.w))));
            b0 = fmaxf(b0, fmaf(r1.x, wc0.x, fmaf(r1.y, wc0.y, fmaf(r1.z, wc0.z, r1.w * wc0.w))));
            a1 = fmaxf(a1, fmaf(r0.x, wc1.x, fmaf(r0.y, wc1.y, fmaf(r0.z, wc1.z, r0.w * wc1.w))));
            b1 = fmaxf(b1, fmaf(r1.x, wc1.x, fmaf(r1.y, wc1.y, fmaf(r1.z, wc1.z, r1.w * wc1.w))));
            r0 = s4[p + 2];
            r1 = s4[p + 3];
            a0 = fmaxf(a0, fmaf(r0.x, wc0.x, fmaf(r0.y, wc0.y, fmaf(r0.z, wc0.z, r0.w * wc0.w))));
            b0 = fmaxf(b0, fmaf(r1.x, wc0.x, fmaf(r1.y, wc0.y, fmaf(r1.z, wc0.z, r1.w * wc0.w))));
            a1 = fmaxf(a1, fmaf(r0.x, wc1.x, fmaf(r0.y, wc1.y, fmaf(r0.z, wc1.z, r0.w * wc1.w))));
            b1 = fmaxf(b1, fmaf(r1.x, wc1.x, fmaf(r1.y, wc1.y, fmaf(r1.z, wc1.z, r1.w * wc1.w))));
        }
        __syncwarp();

        const float pb0 = t0v.z - (pm.x * m0v.x + pm.y * m0v.y + pm.z * m0v.z)
                                - (pc.x * m0v.w + pc.y * t0v.x + pc.z * t0v.y);
        const float pb1 = t1v.z - (pm.x * m1v.x + pm.y * m1v.y + pm.z * m1v.z)
                                - (pc.x * m1v.w + pc.y * t1v.x + pc.z * t1v.y);

        float r0 = pb0 + fmaxf(a0, b0);
        float r1 = pb1 + fmaxf(a1, b1);
        if (nv < PPTS) {   // masked points contribute exactly b pre-ReLU
            r0 = fmaxf(r0, t0v.z);
            r1 = fmaxf(r1, t1v.z);
        }
        out[i * 64 + lane]      = fmaxf(r0, 0.0f);
        out[i * 64 + 32 + lane] = fmaxf(r1, 0.0f);

        if (!more) break;
        i = inext; q = qn; nv = nvn;
    }
}

extern "C" void kernel_launch(void* const* d_in, const int* in_sizes, int n_in,
                              void* d_out, int out_size) {
    const float4* feats  = (const float4*)d_in[0];
    const int*    nvs    = (const int*)d_in[1];
    const int4*   coords = (const int4*)d_in[2];
    const float*  W      = (const float*)d_in[3];
    const float*  gamma  = (const float*)d_in[4];
    const float*  beta   = (const float*)d_in[5];
    float* out = (float*)d_out;

    k_stats<<<SBLK, 128>>>(feats, nvs, coords);
    k_bn<<<1, 544>>>(W, gamma, beta);
    k_out<<<592, 256>>>(feats, nvs, out);
}